// round 13
// baseline (speedup 1.0000x reference)
#include <cuda_runtime.h>
#include <cstdint>

#define BATCH 32
#define HH 512
#define WW 512
#define WPR 16              // u32 words per row (512 bits)
#define RPB 16              // rows per CTA in phase A
#define NBLK_Y (HH / RPB)   // 32
#define PITCH 520           // padded shared row pitch (floats)
#define XOFF 4              // data starts at float index 4 (16B aligned), sentinels at 3 and 516

typedef unsigned long long u64;

// ---------------- global scratch (no allocation allowed) ----------------
__device__ __align__(16) unsigned g_maskP[BATCH * HH * WPR];
__device__ __align__(16) unsigned g_maskG[BATCH * HH * WPR];
__device__ double g_sums[BATCH][3];   // 0: sum p, 1: sum g, 2: sum p*g
__device__ int    g_cnt[BATCH][9];    // pe,ge,pei, pm,gm,pmi, pj,gj,pji
__device__ int    g_dist[2][BATCH];   // sum of clamped chebyshev distances (atomic acc)
__device__ int    g_non[2][BATCH];    // count of target-on pixels (atomic acc)

// ---------------- phase A: smem stencil, float4 staging, fused dice ----------------
__global__ void __launch_bounds__(512) phaseA(const float* __restrict__ pred,
                                              const float* __restrict__ gt) {
    extern __shared__ float smemA[];
    float* sp = smemA;                        // (RPB+2) x PITCH
    float* sg = smemA + (RPB + 2) * PITCH;
    __shared__ float rf[16][3];
    __shared__ int   ri[16][5];

    int blk = blockIdx.x;
    int b   = blk >> 5;                 // / NBLK_Y (=32)
    int r0  = (blk & 31) * RPB;
    int t   = threadIdx.x;
    int x   = t;                        // column 0..511
    int xx  = x + XOFF;

    const float4* pb4 = (const float4*)(pred + (size_t)b * HH * WW);
    const float4* gb4 = (const float4*)(gt   + (size_t)b * HH * WW);

    // ---- staging: float4 loads, dice sums fused (core rows only) ----
    float dp = 0.f, dg = 0.f, dpg = 0.f;
    const int NV = (RPB + 2) * 128;     // float4 slots in the band
    for (int idx = t; idx < NV; idx += 512) {
        int row = idx >> 7, q = idx & 127;
        int gr = r0 - 1 + row;
        float4 pv = make_float4(0.f, 0.f, 0.f, 0.f);
        float4 gv = make_float4(0.f, 0.f, 0.f, 0.f);
        if (gr >= 0 && gr < HH) {
            pv = pb4[(size_t)gr * 128 + q];
            gv = gb4[(size_t)gr * 128 + q];
        }
        ((float4*)(sp + row * PITCH + XOFF))[q] = pv;
        ((float4*)(sg + row * PITCH + XOFF))[q] = gv;
        if (row >= 1 && row <= RPB) {
            dp  += (pv.x + pv.y) + (pv.z + pv.w);
            dg  += (gv.x + gv.y) + (gv.z + gv.w);
            dpg += pv.x * gv.x + pv.y * gv.y + pv.z * gv.z + pv.w * gv.w;
        }
    }
    if (t < RPB + 2) {
        sp[t * PITCH + XOFF - 1] = 0.f;  sp[t * PITCH + XOFF + WW] = 0.f;
        sg[t * PITCH + XOFF - 1] = 0.f;  sg[t * PITCH + XOFF + WW] = 0.f;
    }
    __syncthreads();

    // ---- stencil: rolling horizontal sums + rolling centers ----
    int c0=0,c1=0,c2=0,c3=0,c4=0,c5=0,c6=0,c7=0,c8=0;

    float pcCur, gcCur, pcNext, gcNext;
    float rsp0, rsp1, rsp2, rsg0, rsg1, rsg2;
    {
        float a, cen, c;
        a = sp[xx-1]; cen = sp[xx]; c = sp[xx+1];                 rsp0 = a + cen + c;
        a = sg[xx-1]; cen = sg[xx]; c = sg[xx+1];                 rsg0 = a + cen + c;
        a = sp[PITCH+xx-1]; cen = sp[PITCH+xx]; c = sp[PITCH+xx+1]; rsp1 = a + cen + c; pcCur = cen;
        a = sg[PITCH+xx-1]; cen = sg[PITCH+xx]; c = sg[PITCH+xx+1]; rsg1 = a + cen + c; gcCur = cen;
    }

    #pragma unroll
    for (int y = 0; y < RPB; y++) {
        int rw = (y + 2) * PITCH;
        {
            float a, cen, c;
            a = sp[rw+xx-1]; cen = sp[rw+xx]; c = sp[rw+xx+1]; rsp2 = a + cen + c; pcNext = cen;
            a = sg[rw+xx-1]; cen = sg[rw+xx]; c = sg[rw+xx+1]; rsg2 = a + cen + c; gcNext = cen;
        }
        float p = pcCur, g = gcCur;
        float np = (rsp0 + rsp1 + rsp2) - p;   // 8-neighbor sum (pred, continuous)
        float ng = (rsg0 + rsg1 + rsg2) - g;   // 8-neighbor sum (gt, exact int)
        bool pon = p > 0.5f, gon = g > 0.5f;

        bool pe = pon && (np == 1.f), pm = pon && (np == 2.f), pj = pon && (np > 2.f);
        bool ge = gon && (ng == 1.f), gm = gon && (ng == 2.f), gj = gon && (ng > 2.f);
        c0 += pe; c1 += ge; c2 += (pe && ge);
        c3 += pm; c4 += gm; c5 += (pm && gm);
        c6 += pj; c7 += gj; c8 += (pj && gj);

        unsigned mp = __ballot_sync(0xffffffffu, pon);
        unsigned mg = __ballot_sync(0xffffffffu, gon);
        if ((x & 31) == 0) {
            int w = x >> 5;
            g_maskP[((size_t)b * HH + r0 + y) * WPR + w] = mp;
            g_maskG[((size_t)b * HH + r0 + y) * WPR + w] = mg;
        }
        rsp0 = rsp1; rsp1 = rsp2;
        rsg0 = rsg1; rsg1 = rsg2;
        pcCur = pcNext; gcCur = gcNext;
    }

    // ---- reduce: 3 floats + 9 counters packed into u16 pairs (<=16 each) ----
    int u0 = c0 | (c1 << 16);
    int u1 = c2 | (c3 << 16);
    int u2 = c4 | (c5 << 16);
    int u3 = c6 | (c7 << 16);
    int u4 = c8;
    float a0 = dp, a1 = dg, a2 = dpg;

    #pragma unroll
    for (int o = 16; o > 0; o >>= 1) {
        a0 += __shfl_down_sync(0xffffffffu, a0, o);
        a1 += __shfl_down_sync(0xffffffffu, a1, o);
        a2 += __shfl_down_sync(0xffffffffu, a2, o);
        u0 += __shfl_down_sync(0xffffffffu, u0, o);
        u1 += __shfl_down_sync(0xffffffffu, u1, o);
        u2 += __shfl_down_sync(0xffffffffu, u2, o);
        u3 += __shfl_down_sync(0xffffffffu, u3, o);
        u4 += __shfl_down_sync(0xffffffffu, u4, o);
    }
    int wid = t >> 5, lane = t & 31;
    if (lane == 0) {
        rf[wid][0] = a0; rf[wid][1] = a1; rf[wid][2] = a2;
        ri[wid][0] = u0; ri[wid][1] = u1; ri[wid][2] = u2; ri[wid][3] = u3; ri[wid][4] = u4;
    }
    __syncthreads();
    if (wid == 0) {
        float b0 = (lane < 16) ? rf[lane][0] : 0.f;
        float b1 = (lane < 16) ? rf[lane][1] : 0.f;
        float b2 = (lane < 16) ? rf[lane][2] : 0.f;
        int v0 = (lane < 16) ? ri[lane][0] : 0;
        int v1 = (lane < 16) ? ri[lane][1] : 0;
        int v2 = (lane < 16) ? ri[lane][2] : 0;
        int v3 = (lane < 16) ? ri[lane][3] : 0;
        int v4 = (lane < 16) ? ri[lane][4] : 0;
        #pragma unroll
        for (int o = 8; o > 0; o >>= 1) {
            b0 += __shfl_down_sync(0xffffffffu, b0, o);
            b1 += __shfl_down_sync(0xffffffffu, b1, o);
            b2 += __shfl_down_sync(0xffffffffu, b2, o);
            v0 += __shfl_down_sync(0xffffffffu, v0, o);
            v1 += __shfl_down_sync(0xffffffffu, v1, o);
            v2 += __shfl_down_sync(0xffffffffu, v2, o);
            v3 += __shfl_down_sync(0xffffffffu, v3, o);
            v4 += __shfl_down_sync(0xffffffffu, v4, o);
        }
        if (lane == 0) {
            atomicAdd(&g_sums[b][0], (double)b0);
            atomicAdd(&g_sums[b][1], (double)b1);
            atomicAdd(&g_sums[b][2], (double)b2);
            atomicAdd(&g_cnt[b][0], v0 & 0xffff);
            atomicAdd(&g_cnt[b][1], v0 >> 16);
            atomicAdd(&g_cnt[b][2], v1 & 0xffff);
            atomicAdd(&g_cnt[b][3], v1 >> 16);
            atomicAdd(&g_cnt[b][4], v2 & 0xffff);
            atomicAdd(&g_cnt[b][5], v2 >> 16);
            atomicAdd(&g_cnt[b][6], v3 & 0xffff);
            atomicAdd(&g_cnt[b][7], v3 >> 16);
            atomicAdd(&g_cnt[b][8], v4);
        }
    }
}

// ---------------- phase B: bit-packed chebyshev distance sums, 2 row-chunks ----------------
// Each CTA handles (dir, b, chunk): 256 target rows, ref loaded with 9-row halo.
// After d dilation rounds, local rows [d, LROWS-d) are exact; counted rows
// [HALO, HALO+CROWS) are always within that region for d<=9.
#define CROWS 256
#define HALO  9
#define LROWS (CROWS + 2 * HALO)    // 274
#define LW    (LROWS * 8)           // 2192 u64

__global__ void __launch_bounds__(512) phaseB() {
    extern __shared__ u64 sh[];
    u64* T  = sh;               // 2048 (core target rows)
    u64* A  = sh + 2048;        // 2192
    u64* Bu = A + LW;           // 2192

    int cid = blockIdx.x;       // 0..127
    int ch  = cid & 1;
    int b   = (cid >> 1) & 31;
    int dir = cid >> 6;         // 0: p2g (tgt=pred), 1: g2p (tgt=gt)

    const u64* tgt = (const u64*)(dir == 0 ? g_maskP : g_maskG) + (size_t)b * HH * 8;
    const u64* ref = (const u64*)(dir == 0 ? g_maskG : g_maskP) + (size_t)b * HH * 8;

    int t = threadIdx.x;
    int rbase = ch * CROWS - HALO;

    int non = 0;
    for (int k = t; k < CROWS * 8; k += 512) {
        u64 tv = tgt[(size_t)(ch * CROWS) * 8 + k];
        T[k] = tv;
        non += __popcll(tv);
    }
    for (int k = t; k < LW; k += 512) {
        int gr = rbase + (k >> 3);
        A[k] = (gr >= 0 && gr < HH) ? ref[(size_t)gr * 8 + (k & 7)] : 0ull;
    }
    __syncthreads();

    int cntNot = 0;
    for (int d = 1; d <= 9; d++) {
        // horizontal dilation
        for (int k = t; k < LW; k += 512) {
            int j = k & 7;
            u64 v = A[k];
            u64 h = v | (v << 1) | (v >> 1);
            if (j > 0) h |= A[k - 1] >> 63;
            if (j < 7) h |= A[k + 1] << 63;
            Bu[k] = h;
        }
        __syncthreads();
        // vertical dilation + count uncovered core target bits
        int roundCnt = 0;
        for (int k = t; k < LW; k += 512) {
            int lr = k >> 3;
            u64 v = Bu[k];
            if (lr > 0)         v |= Bu[k - 8];
            if (lr < LROWS - 1) v |= Bu[k + 8];
            A[k] = v;
            if (lr >= HALO && lr < HALO + CROWS)
                roundCnt += __popcll(T[(lr - HALO) * 8 + (k & 7)] & ~v);
        }
        cntNot += roundCnt;
        if (__syncthreads_count(roundCnt) == 0) break;   // also the barrier
    }

    #pragma unroll
    for (int o = 16; o > 0; o >>= 1) {
        non    += __shfl_down_sync(0xffffffffu, non, o);
        cntNot += __shfl_down_sync(0xffffffffu, cntNot, o);
    }
    int* ired = (int*)sh;   // smem fully consumed, last barrier passed
    int wid = t >> 5, lane = t & 31;
    if (lane == 0) { ired[wid * 2] = non; ired[wid * 2 + 1] = cntNot; }
    __syncthreads();
    if (t == 0) {
        int N = 0, C = 0;
        for (int wv = 0; wv < 16; wv++) { N += ired[wv * 2]; C += ired[wv * 2 + 1]; }
        atomicAdd(&g_non[dir][b], N);
        atomicAdd(&g_dist[dir][b], N + C);
    }
}

// ---------------- phase C: final combine (fp32) + re-zero accumulators ----------------
__global__ void phaseC(float* out) {
    int b = threadIdx.x;   // 32 threads
    float dice_t = 0.f, s_t = 0.f, m_t = 0.f;
    if (b < BATCH) {
        float psum  = (float)g_sums[b][0];
        float gsum  = (float)g_sums[b][1];
        float inter = (float)g_sums[b][2];
        dice_t = __fdividef(2.f * inter + 1.f, psum + gsum + 1.f);

        float pe = (float)g_cnt[b][0], ge = (float)g_cnt[b][1], pei = (float)g_cnt[b][2];
        float pm = (float)g_cnt[b][3], gm = (float)g_cnt[b][4], pmi = (float)g_cnt[b][5];
        float pj = (float)g_cnt[b][6], gj = (float)g_cnt[b][7], pji = (float)g_cnt[b][8];
        float e_iou = __fdividef(pei + 1.f, pe + ge - pei + 1.f);
        float m_iou = __fdividef(pmi + 1.f, pm + gm - pmi + 1.f);
        float j_iou = __fdividef(pji + 1.f, pj + gj - pji + 1.f);
        float total = ge + gj + gm + 1.f;
        s_t = 1.f - __fdividef(ge * e_iou + gj * j_iou + gm * m_iou, total);

        float p2g = __fdividef((float)g_dist[0][b], (float)g_non[0][b] + 1.f);
        float g2p = __fdividef((float)g_dist[1][b], (float)g_non[1][b] + 1.f);
        m_t = ((p2g + g2p) * 0.5f) * 0.1f;

        // re-zero accumulators for the next graph replay (each thread owns slot b)
        g_sums[b][0] = 0.0; g_sums[b][1] = 0.0; g_sums[b][2] = 0.0;
        #pragma unroll
        for (int i = 0; i < 9; i++) g_cnt[b][i] = 0;
        g_dist[0][b] = 0; g_dist[1][b] = 0;
        g_non[0][b]  = 0; g_non[1][b]  = 0;
    }
    #pragma unroll
    for (int o = 16; o > 0; o >>= 1) {
        dice_t += __shfl_down_sync(0xffffffffu, dice_t, o);
        s_t    += __shfl_down_sync(0xffffffffu, s_t, o);
        m_t    += __shfl_down_sync(0xffffffffu, m_t, o);
    }
    if (b == 0) {
        float dice_loss = 1.f - dice_t * (1.f / BATCH);
        float s = s_t * (1.f / BATCH);
        float m = m_t * (1.f / BATCH);
        float avg = (dice_loss + s + m) * (1.f / 3.f);
        float r = __fdividef(dice_loss, dice_loss + 1.f) * avg
                + __fdividef(s, s + 1.f) * avg
                + __fdividef(m, m + 1.f) * avg;
        out[0] = r;
    }
}

// ---------------- launch ----------------
extern "C" void kernel_launch(void* const* d_in, const int* in_sizes, int n_in,
                              void* d_out, int out_size) {
    const float* pred = (const float*)d_in[0];
    const float* gt   = (const float*)d_in[1];
    (void)in_sizes; (void)n_in; (void)out_size;

    const int ASMEM = 2 * (RPB + 2) * PITCH * (int)sizeof(float);   // 74880 bytes
    const int BSMEM = (2048 + 2 * LW) * (int)sizeof(u64);           // 51456 bytes
    cudaFuncSetAttribute(phaseA, cudaFuncAttributeMaxDynamicSharedMemorySize, ASMEM);
    cudaFuncSetAttribute(phaseB, cudaFuncAttributeMaxDynamicSharedMemorySize, BSMEM);

    phaseA<<<BATCH * NBLK_Y, 512, ASMEM>>>(pred, gt);
    phaseB<<<128, 512, BSMEM>>>();
    phaseC<<<1, 32>>>((float*)d_out);
}